// round 1
// baseline (speedup 1.0000x reference)
#include <cuda_runtime.h>
#include <math.h>

// Problem constants
constexpr int I_SZ = 256;   // groups
constexpr int D_SZ = 128;   // per-group dim
constexpr int B_SZ = 1024;  // batch
constexpr int HD   = I_SZ * D_SZ;  // 32768
constexpr int TB   = 64;    // batch rows per block tile
constexpr int NTHREADS = 256;

// dynamic smem layout (floats):
//   a_s  [TB][D]   : A tile (hg or rh)                  8192
//   U_s  [D][D]    : current U operand                 16384
//   w1_s [D], w2_s[D], b1_s[D], b2_s[D]                  512
//   x_s  [TB]                                             64
constexpr int SMEM_FLOATS = TB * D_SZ + D_SZ * D_SZ + 4 * D_SZ + TB;
constexpr size_t SMEM_BYTES = (size_t)SMEM_FLOATS * sizeof(float);

__device__ __forceinline__ float sigmoid_fast(float x) {
    return 1.0f / (1.0f + __expf(-x));
}

// Shared GEMM core: acc[4][8] += A_tile(rows r0..r0+3) * U_s (K=128)
#define GEMM_CORE(a_s, U_s, acc, r0, c0)                                        \
    do {                                                                        \
        _Pragma("unroll 4")                                                     \
        for (int k = 0; k < D_SZ; k++) {                                        \
            float a0 = (a_s)[((r0) + 0) * D_SZ + k];                            \
            float a1 = (a_s)[((r0) + 1) * D_SZ + k];                            \
            float a2 = (a_s)[((r0) + 2) * D_SZ + k];                            \
            float a3 = (a_s)[((r0) + 3) * D_SZ + k];                            \
            float4 bA = *(const float4*)&(U_s)[k * D_SZ + (c0)];                \
            float4 bB = *(const float4*)&(U_s)[k * D_SZ + (c0) + 4];            \
            float bv[8] = {bA.x, bA.y, bA.z, bA.w, bB.x, bB.y, bB.z, bB.w};     \
            _Pragma("unroll")                                                   \
            for (int cc = 0; cc < 8; cc++) {                                    \
                acc[0][cc] = fmaf(a0, bv[cc], acc[0][cc]);                      \
                acc[1][cc] = fmaf(a1, bv[cc], acc[1][cc]);                      \
                acc[2][cc] = fmaf(a2, bv[cc], acc[2][cc]);                      \
                acc[3][cc] = fmaf(a3, bv[cc], acc[3][cc]);                      \
            }                                                                   \
        }                                                                       \
    } while (0)

// Phase 1: r = sigmoid(x*W_r + hg@U_r + b_r); z = sigmoid(x*W_z + hg@U_z + b_z)
// Writes rh = r*hg into out_ht region, z into out_hnew region (temporaries).
__global__ __launch_bounds__(NTHREADS) void gru_phase1(
    const float* __restrict__ X, const float* __restrict__ h,
    const float* __restrict__ W_r, const float* __restrict__ W_z,
    const float* __restrict__ U_r, const float* __restrict__ U_z,
    const float* __restrict__ b_r, const float* __restrict__ b_z,
    float* __restrict__ out_hnew, float* __restrict__ out_ht)
{
    extern __shared__ float smem[];
    float* a_s  = smem;
    float* U_s  = smem + TB * D_SZ;
    float* w1_s = U_s + D_SZ * D_SZ;
    float* w2_s = w1_s + D_SZ;
    float* b1_s = w2_s + D_SZ;
    float* b2_s = b1_s + D_SZ;
    float* x_s  = b2_s + D_SZ;

    const int i   = blockIdx.y;
    const int b0  = blockIdx.x * TB;
    const int tid = threadIdx.x;

    // Load hg tile [TB][D]
    for (int t = tid; t < TB * D_SZ / 4; t += NTHREADS) {
        int row = t >> 5;   // 32 float4 per row
        int c4  = t & 31;
        ((float4*)a_s)[t] =
            ((const float4*)(h + (size_t)(b0 + row) * HD + (size_t)i * D_SZ))[c4];
    }
    // Load U_r
    {
        const float4* u4 = (const float4*)(U_r + (size_t)i * D_SZ * D_SZ);
        for (int t = tid; t < D_SZ * D_SZ / 4; t += NTHREADS)
            ((float4*)U_s)[t] = u4[t];
    }
    if (tid < D_SZ) {
        w1_s[tid] = W_r[i * D_SZ + tid];
        w2_s[tid] = W_z[i * D_SZ + tid];
        b1_s[tid] = b_r[i * D_SZ + tid];
        b2_s[tid] = b_z[i * D_SZ + tid];
    }
    if (tid < TB) x_s[tid] = X[(size_t)(b0 + tid) * I_SZ + i];
    __syncthreads();

    const int tc = tid & 15, trg = tid >> 4;
    const int r0 = trg * 4, c0 = tc * 8;

    float acc[4][8];
#pragma unroll
    for (int a = 0; a < 4; a++)
#pragma unroll
        for (int b = 0; b < 8; b++) acc[a][b] = 0.0f;

    GEMM_CORE(a_s, U_s, acc, r0, c0);
    __syncthreads();  // all threads done reading U_r before overwrite

    // Epilogue r -> write rh = r*hg into out_ht
#pragma unroll
    for (int rr = 0; rr < 4; rr++) {
        int row = r0 + rr;
        float xv = x_s[row];
        float o[8];
#pragma unroll
        for (int cc = 0; cc < 8; cc++) {
            int k = c0 + cc;
            float pre = acc[rr][cc] + xv * w1_s[k] + b1_s[k];
            float r = sigmoid_fast(pre);
            o[cc] = r * a_s[row * D_SZ + k];
        }
        float* dst = out_ht + (size_t)(b0 + row) * HD + (size_t)i * D_SZ + c0;
        ((float4*)dst)[0] = make_float4(o[0], o[1], o[2], o[3]);
        ((float4*)dst)[1] = make_float4(o[4], o[5], o[6], o[7]);
    }

    // Load U_z over U_s
    {
        const float4* u4 = (const float4*)(U_z + (size_t)i * D_SZ * D_SZ);
        for (int t = tid; t < D_SZ * D_SZ / 4; t += NTHREADS)
            ((float4*)U_s)[t] = u4[t];
    }
    __syncthreads();

#pragma unroll
    for (int a = 0; a < 4; a++)
#pragma unroll
        for (int b = 0; b < 8; b++) acc[a][b] = 0.0f;

    GEMM_CORE(a_s, U_s, acc, r0, c0);

    // Epilogue z -> write z into out_hnew (temporary storage)
#pragma unroll
    for (int rr = 0; rr < 4; rr++) {
        int row = r0 + rr;
        float xv = x_s[row];
        float o[8];
#pragma unroll
        for (int cc = 0; cc < 8; cc++) {
            int k = c0 + cc;
            float pre = acc[rr][cc] + xv * w2_s[k] + b2_s[k];
            o[cc] = sigmoid_fast(pre);
        }
        float* dst = out_hnew + (size_t)(b0 + row) * HD + (size_t)i * D_SZ + c0;
        ((float4*)dst)[0] = make_float4(o[0], o[1], o[2], o[3]);
        ((float4*)dst)[1] = make_float4(o[4], o[5], o[6], o[7]);
    }
}

// Phase 2: h_tilde = tanh(x*W_h + rh@U_h + b_h); h_new = z*hg + (1-z)*h_tilde.
// Reads rh from out_ht and z from out_hnew (rows owned by this block only),
// overwrites them with h_tilde / h_new in place.
__global__ __launch_bounds__(NTHREADS) void gru_phase2(
    const float* __restrict__ X, const float* __restrict__ h,
    const float* __restrict__ W_h, const float* __restrict__ U_h,
    const float* __restrict__ b_h,
    float* __restrict__ out_hnew, float* __restrict__ out_ht)
{
    extern __shared__ float smem[];
    float* a_s  = smem;                 // rh tile
    float* U_s  = smem + TB * D_SZ;
    float* w1_s = U_s + D_SZ * D_SZ;
    float* b1_s = w1_s + D_SZ;          // reuse slots; only need 2 small arrays
    float* x_s  = b1_s + D_SZ;

    const int i   = blockIdx.y;
    const int b0  = blockIdx.x * TB;
    const int tid = threadIdx.x;

    // Load rh tile from out_ht
    for (int t = tid; t < TB * D_SZ / 4; t += NTHREADS) {
        int row = t >> 5;
        int c4  = t & 31;
        ((float4*)a_s)[t] =
            ((const float4*)(out_ht + (size_t)(b0 + row) * HD + (size_t)i * D_SZ))[c4];
    }
    {
        const float4* u4 = (const float4*)(U_h + (size_t)i * D_SZ * D_SZ);
        for (int t = tid; t < D_SZ * D_SZ / 4; t += NTHREADS)
            ((float4*)U_s)[t] = u4[t];
    }
    if (tid < D_SZ) {
        w1_s[tid] = W_h[i * D_SZ + tid];
        b1_s[tid] = b_h[i * D_SZ + tid];
    }
    if (tid < TB) x_s[tid] = X[(size_t)(b0 + tid) * I_SZ + i];
    __syncthreads();

    const int tc = tid & 15, trg = tid >> 4;
    const int r0 = trg * 4, c0 = tc * 8;

    float acc[4][8];
#pragma unroll
    for (int a = 0; a < 4; a++)
#pragma unroll
        for (int b = 0; b < 8; b++) acc[a][b] = 0.0f;

    GEMM_CORE(a_s, U_s, acc, r0, c0);

    // Fused epilogue: h_tilde + final gate combine
#pragma unroll
    for (int rr = 0; rr < 4; rr++) {
        int row = r0 + rr;
        float xv = x_s[row];
        size_t gbase = (size_t)(b0 + row) * HD + (size_t)i * D_SZ + c0;

        float4 z1 = ((const float4*)(out_hnew + gbase))[0];
        float4 z2 = ((const float4*)(out_hnew + gbase))[1];
        float4 g1 = ((const float4*)(h + gbase))[0];
        float4 g2 = ((const float4*)(h + gbase))[1];
        float zv[8] = {z1.x, z1.y, z1.z, z1.w, z2.x, z2.y, z2.z, z2.w};
        float gv[8] = {g1.x, g1.y, g1.z, g1.w, g2.x, g2.y, g2.z, g2.w};

        float ht[8], hn[8];
#pragma unroll
        for (int cc = 0; cc < 8; cc++) {
            int k = c0 + cc;
            float pre = acc[rr][cc] + xv * w1_s[k] + b1_s[k];
            float t = tanhf(pre);
            ht[cc] = t;
            hn[cc] = zv[cc] * gv[cc] + (1.0f - zv[cc]) * t;
        }
        ((float4*)(out_ht + gbase))[0]   = make_float4(ht[0], ht[1], ht[2], ht[3]);
        ((float4*)(out_ht + gbase))[1]   = make_float4(ht[4], ht[5], ht[6], ht[7]);
        ((float4*)(out_hnew + gbase))[0] = make_float4(hn[0], hn[1], hn[2], hn[3]);
        ((float4*)(out_hnew + gbase))[1] = make_float4(hn[4], hn[5], hn[6], hn[7]);
    }
}

extern "C" void kernel_launch(void* const* d_in, const int* in_sizes, int n_in,
                              void* d_out, int out_size) {
    const float* X  = (const float*)d_in[0];
    const float* h  = (const float*)d_in[1];
    const float* Wr = (const float*)d_in[2];
    const float* Wz = (const float*)d_in[3];
    const float* Wh = (const float*)d_in[4];
    const float* Ur = (const float*)d_in[5];
    const float* Uz = (const float*)d_in[6];
    const float* Uh = (const float*)d_in[7];
    const float* br = (const float*)d_in[8];
    const float* bz = (const float*)d_in[9];
    const float* bh = (const float*)d_in[10];

    float* out      = (float*)d_out;
    float* out_hnew = out;                           // first output of tuple
    float* out_ht   = out + (size_t)B_SZ * HD;       // second output of tuple

    cudaFuncSetAttribute(gru_phase1, cudaFuncAttributeMaxDynamicSharedMemorySize,
                         (int)SMEM_BYTES);
    cudaFuncSetAttribute(gru_phase2, cudaFuncAttributeMaxDynamicSharedMemorySize,
                         (int)SMEM_BYTES);

    dim3 grid(B_SZ / TB, I_SZ);  // x = batch tile (fast) -> U reuse in L2 across a wave
    gru_phase1<<<grid, NTHREADS, SMEM_BYTES>>>(X, h, Wr, Wz, Ur, Uz, br, bz,
                                               out_hnew, out_ht);
    gru_phase2<<<grid, NTHREADS, SMEM_BYTES>>>(X, h, Wh, Uh, bh, out_hnew, out_ht);
}